// round 13
// baseline (speedup 1.0000x reference)
#include <cuda_runtime.h>
#include <cuda_bf16.h>
#include <cstdint>
#include <cstddef>

#define B_   16
#define S_   2048
#define D_   256
#define GD_  1024
#define L_   4
#define NTOK (B_*S_)
#define CL   8
#define FULLM 0xffffffffu

// ---- scratch (device globals: no allocations allowed) ----
__device__ float g_h  [(size_t)NTOK*D_];      // residual stream [B,S,D]
__device__ float g_gx [(size_t)NTOK*GD_];     // gate preacts    [B,S,4D]
__device__ float g_mu [NTOK];
__device__ float g_rs [NTOK];
__device__ float g_whT[(size_t)L_*GD_*D_];    // Wh transposed: [l][col][k]

typedef unsigned long long ull;

__device__ __forceinline__ ull pack2(float x, float y){
    ull r; asm("mov.b64 %0,{%1,%2};" : "=l"(r) : "f"(x), "f"(y)); return r;
}
__device__ __forceinline__ float2 unpack2(ull v){
    float2 f; asm("mov.b64 {%0,%1},%2;" : "=f"(f.x), "=f"(f.y) : "l"(v)); return f;
}
__device__ __forceinline__ void fma2(ull& d, ull a, ull b){
    asm("fma.rn.f32x2 %0,%1,%2,%0;" : "+l"(d) : "l"(a), "l"(b));
}
__device__ __forceinline__ void add2(ull& d, ull a){
    asm("add.rn.f32x2 %0,%0,%1;" : "+l"(d) : "l"(a));
}
__device__ __forceinline__ float frcp(float x){
    float r; asm("rcp.approx.f32 %0,%1;" : "=f"(r) : "f"(x)); return r;
}
__device__ __forceinline__ float ftanh(float x){
    float r; asm("tanh.approx.f32 %0,%1;" : "=f"(r) : "f"(x)); return r;
}

// ============================================================
// 1) input projection
// ============================================================
__global__ void k_inproj(const float* __restrict__ x, const float* __restrict__ tf,
                         const float* __restrict__ W, const float* __restrict__ b)
{
    int t = blockIdx.x, d = threadIdx.x;
    float acc = b[d] + x[t]*W[d];
    const float* tft = tf + (size_t)t*6;
    #pragma unroll
    for(int f=0; f<6; f++) acc = fmaf(tft[f], W[(f+1)*D_ + d], acc);
    g_h[(size_t)t*D_ + d] = acc;
}

// ============================================================
// 2) per-token layernorm stats
// ============================================================
__global__ void k_lnstats()
{
    int warp = threadIdx.x >> 5, lane = threadIdx.x & 31;
    int t = blockIdx.x*8 + warp;
    const float4* p = (const float4*)(g_h + (size_t)t*D_) + lane*2;
    float4 v0 = p[0], v1 = p[1];
    float s = v0.x+v0.y+v0.z+v0.w + v1.x+v1.y+v1.z+v1.w;
    float q = v0.x*v0.x+v0.y*v0.y+v0.z*v0.z+v0.w*v0.w
            + v1.x*v1.x+v1.y*v1.y+v1.z*v1.z+v1.w*v1.w;
    #pragma unroll
    for(int o=16;o;o>>=1){ s += __shfl_xor_sync(~0u,s,o); q += __shfl_xor_sync(~0u,q,o); }
    if(lane==0){
        float mu  = s * (1.f/256.f);
        float var = q * (1.f/256.f) - mu*mu;
        g_mu[t] = mu;
        g_rs[t] = rsqrtf(var + 1e-5f);
    }
}

// ============================================================
// 2b) Wh transpose: g_whT[l][c][k] = Wh[l][k][c]
// ============================================================
__global__ void k_whT(const float* __restrict__ Wh)
{
    __shared__ float tile[32][33];
    int l = blockIdx.z;
    const float* src = Wh + (size_t)l*D_*GD_;
    float* dst = g_whT + (size_t)l*GD_*D_;
    int c0 = blockIdx.x*32, k0 = blockIdx.y*32;
    int tx = threadIdx.x, ty = threadIdx.y;
    #pragma unroll
    for(int r=0;r<32;r+=8) tile[ty+r][tx] = src[(size_t)(k0+ty+r)*GD_ + c0+tx];
    __syncthreads();
    #pragma unroll
    for(int r=0;r<32;r+=8) dst[(size_t)(c0+ty+r)*D_ + k0+tx] = tile[tx][ty+r];
}

// ============================================================
// 3) gx = (LN(h)*g+b) @ Wx + bg   (128x128 tile, f32x2 accs)
// ============================================================
__global__ __launch_bounds__(256)
void k_gemm(const float* __restrict__ Wx, const float* __restrict__ bg,
            const float* __restrict__ lng, const float* __restrict__ lnb)
{
    __shared__ __align__(16) float As[8*128];
    __shared__ __align__(16) float Bs[8*128];

    int tid = threadIdx.x;
    int m0 = blockIdx.y*128, n0 = blockIdx.x*128;
    int tx = tid & 15, ty = tid >> 4;

    ull acc[8][4];
    #pragma unroll
    for(int i=0;i<8;i++)
        #pragma unroll
        for(int j=0;j<4;j++) acc[i][j]=0ULL;

    int arow = tid>>1, akp = (tid&1)*4;
    float amu = g_mu[m0+arow], ars = g_rs[m0+arow];
    int bkk = tid>>5, bn = (tid&31)*4;

    for(int kb=0; kb<D_; kb+=8){
        float4 av = *(const float4*)(g_h + (size_t)(m0+arow)*D_ + kb + akp);
        float4 lg = *(const float4*)(lng + kb + akp);
        float4 lb = *(const float4*)(lnb + kb + akp);
        As[(akp+0)*128+arow] = (av.x-amu)*ars*lg.x + lb.x;
        As[(akp+1)*128+arow] = (av.y-amu)*ars*lg.y + lb.y;
        As[(akp+2)*128+arow] = (av.z-amu)*ars*lg.z + lb.z;
        As[(akp+3)*128+arow] = (av.w-amu)*ars*lg.w + lb.w;
        *(float4*)(Bs + bkk*128 + bn) =
            *(const float4*)(Wx + (size_t)(kb+bkk)*GD_ + n0 + bn);
        __syncthreads();
        #pragma unroll
        for(int kk=0; kk<8; kk++){
            float4 a0 = *(const float4*)(As + kk*128 + ty*8);
            float4 a1 = *(const float4*)(As + kk*128 + ty*8 + 4);
            const ull* b2 = (const ull*)(Bs + kk*128 + tx*8);
            ull bb0=b2[0], bb1=b2[1], bb2=b2[2], bb3=b2[3];
            float a[8] = {a0.x,a0.y,a0.z,a0.w,a1.x,a1.y,a1.z,a1.w};
            #pragma unroll
            for(int i=0;i<8;i++){
                ull a2 = pack2(a[i], a[i]);
                fma2(acc[i][0], a2, bb0);
                fma2(acc[i][1], a2, bb1);
                fma2(acc[i][2], a2, bb2);
                fma2(acc[i][3], a2, bb3);
            }
        }
        __syncthreads();
    }
    float4 bg0 = *(const float4*)(bg + n0 + tx*8);
    float4 bg1 = *(const float4*)(bg + n0 + tx*8 + 4);
    #pragma unroll
    for(int i=0;i<8;i++){
        float* C = g_gx + (size_t)(m0+ty*8+i)*GD_ + n0 + tx*8;
        float2 c0=unpack2(acc[i][0]), c1=unpack2(acc[i][1]);
        float2 c2=unpack2(acc[i][2]), c3=unpack2(acc[i][3]);
        *(float4*)C       = make_float4(c0.x+bg0.x, c0.y+bg0.y, c1.x+bg0.z, c1.y+bg0.w);
        *(float4*)(C + 4) = make_float4(c2.x+bg1.x, c2.y+bg1.y, c3.x+bg1.z, c3.y+bg1.w);
    }
}

// ============================================================
// 4) sLSTM recurrence — barrier-free warp-autonomous pipeline.
//    Cluster 8, 256 thr/CTA. CTA rank owns dims [rank*32,+32).
//    Warp w owns dims rank*32+4w..+4 with ALL 4 gates (16 cols,
//    2 threads/col split over k). Gating is warp-local.
//    Cross-CTA: 64 monotonic stamp flags (one per producer warp),
//    st.release push / ld.acquire spin. NO cluster barrier, NO
//    __syncthreads in the 2048-step loop.
// ============================================================

#define SSTEP(T, CUR, FL, RH, RF)                                              \
{                                                                              \
    /* ---- spin until all 64 producer-warp stamps of buf CUR >= T */          \
    {                                                                          \
        int f1, f2;                                                            \
        do {                                                                   \
            asm volatile("ld.acquire.cluster.shared::cta.u32 %0, [%1];"        \
                         : "=r"(f1) : "r"(FL)       : "memory");               \
            asm volatile("ld.acquire.cluster.shared::cta.u32 %0, [%1];"        \
                         : "=r"(f2) : "r"(FL + 128) : "memory");               \
        } while(!__all_sync(FULLM, (f1 >= (T)) && (f2 >= (T))));               \
    }                                                                          \
    asm volatile("cp.async.wait_group 3;" ::: "memory");                       \
    __syncwarp();                                                              \
    /* ---- consume prefetched gx / residual for this step */                  \
    int slot = (T) & 3;                                                        \
    float gxi=0.f,gxf=0.f,gxz=0.f,gxo=0.f,hres=0.f;                            \
    if(lane < 4){                                                              \
        const float* gb = &gxbuf[slot][warp*16 + lane];                        \
        gxi = gb[0]; gxf = gb[4]; gxz = gb[8]; gxo = gb[12];                   \
        hres = hrbuf[slot][warp*4 + lane];                                     \
    }                                                                          \
    __syncwarp();                                                              \
    /* ---- refill slot with step T+4 */                                       \
    if((T)+4 < S_){                                                            \
        if(lane < 4){                                                          \
            uint32_t dgx = gxsa + (uint32_t)slot*512u;                         \
            const float* sg = gx_b + (size_t)((T)+4)*GD_ + gx_off;             \
            asm volatile("cp.async.cg.shared.global [%0], [%1], 16;"           \
                         :: "r"(dgx), "l"(sg));                                \
        } else if(lane == 4){                                                  \
            uint32_t dhr = hrsa + (uint32_t)slot*128u;                         \
            const float* sh = h_bp + (size_t)((T)+4)*D_ + hr_off;              \
            asm volatile("cp.async.cg.shared.global [%0], [%1], 16;"           \
                         :: "r"(dhr), "l"(sh));                                \
        }                                                                      \
    }                                                                          \
    asm volatile("cp.async.commit_group;" ::: "memory");                       \
    /* ---- matvec over my k-half for my 16 columns' share */                  \
    const ull* hu = (const ull*)h_buf[CUR];                                    \
    ull a0=0ULL, a1=0ULL, a2v=0ULL, a3=0ULL;                                   \
    _Pragma("unroll")                                                          \
    for(int q=0; q<16; q++){                                                   \
        ulonglong2 U = *(const ulonglong2*)(hu + 8*q + 4*s);                   \
        ulonglong2 V = *(const ulonglong2*)(hu + 8*q + 4*s + 2);               \
        fma2(a0,  U.x, w[4*q+0]);                                              \
        fma2(a1,  U.y, w[4*q+1]);                                              \
        fma2(a2v, V.x, w[4*q+2]);                                              \
        fma2(a3,  V.y, w[4*q+3]);                                              \
    }                                                                          \
    add2(a0, a1); add2(a2v, a3); add2(a0, a2v);                                \
    float2 pp = unpack2(a0);                                                   \
    float v = pp.x + pp.y;                                                     \
    v += __shfl_xor_sync(FULLM, v, 16);                                        \
    /* ---- gather gates to lanes 0..3 (dim j) */                              \
    int src4 = 4*lane;                                                         \
    float vi = __shfl_sync(FULLM, v, src4    );                                \
    float vf = __shfl_sync(FULLM, v, src4 + 1);                                \
    float vz = __shfl_sync(FULLM, v, src4 + 2);                                \
    float vo = __shfl_sync(FULLM, v, src4 + 3);                                \
    float hval = 0.f;                                                          \
    if(lane < 4){                                                              \
        float i_t = vi + gxi, f_t = vf + gxf;                                  \
        float z_t = vz + gxz, o_t = vo + gxo;                                  \
        float m_new = fmaxf(f_t + m_st, i_t);                                  \
        float ip = __expf(i_t - m_new);                                        \
        float fp = __expf(f_t + m_st - m_new);                                 \
        m_st = m_new;                                                          \
        c_st = fp*c_st + ip*ftanh(z_t);                                        \
        n_st = fp*n_st + ip;                                                   \
        float sig  = frcp(1.f + __expf(-o_t));                                 \
        hval = sig * c_st * frcp(fmaxf(fabsf(n_st), 1.f));                     \
        h_bp[(size_t)(T)*D_ + hr_off + lane] = hres + hval;                    \
    }                                                                          \
    /* ---- pack 4 dims and push to all 8 CTAs, then release stamps */         \
    if((T)+1 < S_){                                                            \
        float h4x = __shfl_sync(FULLM, hval, 0);                               \
        float h4y = __shfl_sync(FULLM, hval, 1);                               \
        float h4z = __shfl_sync(FULLM, hval, 2);                               \
        float h4w = __shfl_sync(FULLM, hval, 3);                               \
        if(lane == 0){                                                         \
            _Pragma("unroll")                                                  \
            for(int r=0; r<CL; r++)                                            \
                asm volatile("st.shared::cluster.v4.f32 [%0], {%1,%2,%3,%4};"  \
                             :: "r"(RH[r]), "f"(h4x), "f"(h4y),                \
                                "f"(h4z), "f"(h4w) : "memory");                \
        }                                                                      \
        __syncwarp();                                                          \
        if(lane < 8)                                                           \
            asm volatile("st.release.cluster.shared::cluster.u32 [%0], %1;"    \
                         :: "r"(RF), "r"((T)+1) : "memory");                   \
    }                                                                          \
}

__global__ void __launch_bounds__(256,1) __cluster_dims__(CL,1,1)
k_slstm(int layer)
{
    __shared__ __align__(16) float h_buf[2][256];   // [buf][dim]
    __shared__ __align__(16) int   flg[2][64];      // [buf][producer rank*8+warp]
    __shared__ __align__(16) float gxbuf[4][128];   // [slot][warp*16 + gate*4 + j]
    __shared__ __align__(16) float hrbuf[4][32];    // [slot][warp*4 + j]

    int tid  = threadIdx.x;
    int lane = tid & 31, warp = tid >> 5;
    uint32_t rank;
    asm("mov.u32 %0, %%cluster_ctarank;" : "=r"(rank));
    int batch = blockIdx.x >> 3;

    // column assignment: warp owns dims rank*32+4w..+4, all 4 gates.
    int cw = lane & 15;                 // col within warp
    int s  = lane >> 4;                 // k-half (16-float interleave)
    int dim_l = cw >> 2, gate = cw & 3;
    int gcol = gate*256 + (int)rank*32 + warp*4 + dim_l;

    // register-resident Wh^T: my column's k-half (128 values, 64 f32x2)
    const float* wr = g_whT + (size_t)layer*GD_*D_ + (size_t)gcol*D_;
    ull w[64];
    #pragma unroll
    for(int q=0; q<16; q++){
        float4 A  = *(const float4*)(wr + 16*q + 8*s);
        float4 Bv = *(const float4*)(wr + 16*q + 8*s + 4);
        w[4*q+0] = pack2(A.x,  A.y);
        w[4*q+1] = pack2(A.z,  A.w);
        w[4*q+2] = pack2(Bv.x, Bv.y);
        w[4*q+3] = pack2(Bv.z, Bv.w);
    }

    const float* gx_b = g_gx + (size_t)batch*S_*GD_;
    float*       h_bp = g_h  + (size_t)batch*S_*D_;
    int gx_off = lane*256 + (int)rank*32 + warp*4;   // valid for lane<4
    int hr_off = (int)rank*32 + warp*4;

    // remote addresses (hoisted)
    uint32_t rh0[CL], rh1[CL], rf0, rf1;
    {
        uint32_t l0 = (uint32_t)__cvta_generic_to_shared(&h_buf[0][(int)rank*32 + warp*4]);
        uint32_t l1 = l0 + 1024u;   // h_buf[1]
        #pragma unroll
        for(int r=0; r<CL; r++){
            asm volatile("mapa.shared::cluster.u32 %0, %1, %2;" : "=r"(rh0[r]) : "r"(l0), "r"(r));
            asm volatile("mapa.shared::cluster.u32 %0, %1, %2;" : "=r"(rh1[r]) : "r"(l1), "r"(r));
        }
        uint32_t lf = (uint32_t)__cvta_generic_to_shared(&flg[0][(int)rank*8 + warp]);
        int peer = lane & 7;
        asm volatile("mapa.shared::cluster.u32 %0, %1, %2;" : "=r"(rf0) : "r"(lf),        "r"(peer));
        asm volatile("mapa.shared::cluster.u32 %0, %1, %2;" : "=r"(rf1) : "r"(lf + 256u), "r"(peer));
    }
    // local flag spin addresses (this lane checks 2 of 64)
    uint32_t fl0 = (uint32_t)__cvta_generic_to_shared(&flg[0][lane]);
    uint32_t fl1 = (uint32_t)__cvta_generic_to_shared(&flg[1][lane]);
    // cp.async destinations
    uint32_t gxsa = (uint32_t)__cvta_generic_to_shared(&gxbuf[0][warp*16 + lane*4]); // lane<4
    uint32_t hrsa = (uint32_t)__cvta_generic_to_shared(&hrbuf[0][warp*4]);           // lane==4

    // init
    h_buf[0][tid] = 0.f;
    if(tid < 64){ flg[0][tid] = 0; flg[1][tid] = 0; }
    __syncthreads();
    asm volatile("barrier.cluster.arrive.aligned;" ::: "memory");
    asm volatile("barrier.cluster.wait.aligned;"   ::: "memory");

    // prefill cp.async ring: steps 0..3 (per-warp, per-thread groups)
    #pragma unroll
    for(int pt=0; pt<4; pt++){
        if(lane < 4){
            uint32_t dgx = gxsa + (uint32_t)pt*512u;
            const float* sg = gx_b + (size_t)pt*GD_ + gx_off;
            asm volatile("cp.async.cg.shared.global [%0], [%1], 16;" :: "r"(dgx), "l"(sg));
        } else if(lane == 4){
            uint32_t dhr = hrsa + (uint32_t)pt*128u;
            const float* sh = h_bp + (size_t)pt*D_ + hr_off;
            asm volatile("cp.async.cg.shared.global [%0], [%1], 16;" :: "r"(dhr), "l"(sh));
        }
        asm volatile("cp.async.commit_group;" ::: "memory");
    }

    float c_st=0.f, n_st=0.f, m_st=0.f;

    for(int t=0; t<S_; t+=2){
        SSTEP(t,   0, fl0, rh1, rf1)
        SSTEP(t+1, 1, fl1, rh0, rf0)
    }

    // keep cluster SMEM alive until all CTAs done
    asm volatile("barrier.cluster.arrive.aligned;" ::: "memory");
    asm volatile("barrier.cluster.wait.aligned;"   ::: "memory");
}

// ============================================================
// 5) head: out[b] = h[b, S-1, :] @ fc_W + fc_b
// ============================================================
__global__ void k_head(const float* __restrict__ fcW, const float* __restrict__ fcb,
                       float* __restrict__ out)
{
    __shared__ float red[8];
    int b = blockIdx.x, tid = threadIdx.x;
    int lane = tid & 31, warp = tid >> 5;
    float v = g_h[((size_t)b*S_ + (S_-1))*D_ + tid] * fcW[tid];
    #pragma unroll
    for(int o=16;o;o>>=1) v += __shfl_xor_sync(~0u, v, o);
    if(lane==0) red[warp] = v;
    __syncthreads();
    if(tid==0){
        float s = 0.f;
        #pragma unroll
        for(int w=0;w<8;w++) s += red[w];
        out[b] = s + fcb[0];
    }
}

// ============================================================
extern "C" void kernel_launch(void* const* d_in, const int* in_sizes, int n_in,
                              void* d_out, int out_size)
{
    (void)in_sizes; (void)n_in; (void)out_size;
    const float* x    = (const float*)d_in[0];
    const float* tf   = (const float*)d_in[1];
    const float* in_W = (const float*)d_in[2];
    const float* in_b = (const float*)d_in[3];
    const float* ln_g = (const float*)d_in[4];
    const float* ln_b = (const float*)d_in[5];
    const float* Wx   = (const float*)d_in[6];
    const float* Wh   = (const float*)d_in[7];
    const float* bg   = (const float*)d_in[8];
    const float* fc_W = (const float*)d_in[9];
    const float* fc_b = (const float*)d_in[10];
    float* out = (float*)d_out;

    k_inproj<<<NTOK, 256>>>(x, tf, in_W, in_b);
    k_whT<<<dim3(GD_/32, D_/32, L_), dim3(32,8)>>>(Wh);
    for(int l=0; l<L_; l++){
        k_lnstats<<<NTOK/8, 256>>>();
        k_gemm<<<dim3(8,256), 256>>>(Wx + (size_t)l*D_*GD_, bg + (size_t)l*GD_,
                                     ln_g + (size_t)l*D_, ln_b + (size_t)l*D_);
        k_slstm<<<B_*CL, 256>>>(l);
    }
    k_head<<<B_, 256>>>(fc_W, fc_b, out);
}

// round 14
// speedup vs baseline: 1.4940x; 1.4940x over previous
#include <cuda_runtime.h>
#include <cuda_bf16.h>
#include <cstdint>
#include <cstddef>

#define B_   16
#define S_   2048
#define D_   256
#define GD_  1024
#define L_   4
#define NTOK (B_*S_)
#define CL   8
#define FULLM 0xffffffffu

// ---- scratch (device globals: no allocations allowed) ----
__device__ float g_h  [(size_t)NTOK*D_];      // residual stream [B,S,D]
__device__ float g_gx [(size_t)NTOK*GD_];     // gate preacts    [B,S,4D]
__device__ float g_mu [NTOK];
__device__ float g_rs [NTOK];
__device__ float g_whT[(size_t)L_*GD_*D_];    // Wh transposed: [l][col][k]

typedef unsigned long long ull;

__device__ __forceinline__ ull pack2(float x, float y){
    ull r; asm("mov.b64 %0,{%1,%2};" : "=l"(r) : "f"(x), "f"(y)); return r;
}
__device__ __forceinline__ float2 unpack2(ull v){
    float2 f; asm("mov.b64 {%0,%1},%2;" : "=f"(f.x), "=f"(f.y) : "l"(v)); return f;
}
__device__ __forceinline__ void fma2(ull& d, ull a, ull b){
    asm("fma.rn.f32x2 %0,%1,%2,%0;" : "+l"(d) : "l"(a), "l"(b));
}
__device__ __forceinline__ void add2(ull& d, ull a){
    asm("add.rn.f32x2 %0,%0,%1;" : "+l"(d) : "l"(a));
}
__device__ __forceinline__ float frcp(float x){
    float r; asm("rcp.approx.f32 %0,%1;" : "=f"(r) : "f"(x)); return r;
}
__device__ __forceinline__ float ftanh(float x){
    float r; asm("tanh.approx.f32 %0,%1;" : "=f"(r) : "f"(x)); return r;
}

// ============================================================
// 1) input projection
// ============================================================
__global__ void k_inproj(const float* __restrict__ x, const float* __restrict__ tf,
                         const float* __restrict__ W, const float* __restrict__ b)
{
    int t = blockIdx.x, d = threadIdx.x;
    float acc = b[d] + x[t]*W[d];
    const float* tft = tf + (size_t)t*6;
    #pragma unroll
    for(int f=0; f<6; f++) acc = fmaf(tft[f], W[(f+1)*D_ + d], acc);
    g_h[(size_t)t*D_ + d] = acc;
}

// ============================================================
// 2) per-token layernorm stats
// ============================================================
__global__ void k_lnstats()
{
    int warp = threadIdx.x >> 5, lane = threadIdx.x & 31;
    int t = blockIdx.x*8 + warp;
    const float4* p = (const float4*)(g_h + (size_t)t*D_) + lane*2;
    float4 v0 = p[0], v1 = p[1];
    float s = v0.x+v0.y+v0.z+v0.w + v1.x+v1.y+v1.z+v1.w;
    float q = v0.x*v0.x+v0.y*v0.y+v0.z*v0.z+v0.w*v0.w
            + v1.x*v1.x+v1.y*v1.y+v1.z*v1.z+v1.w*v1.w;
    #pragma unroll
    for(int o=16;o;o>>=1){ s += __shfl_xor_sync(~0u,s,o); q += __shfl_xor_sync(~0u,q,o); }
    if(lane==0){
        float mu  = s * (1.f/256.f);
        float var = q * (1.f/256.f) - mu*mu;
        g_mu[t] = mu;
        g_rs[t] = rsqrtf(var + 1e-5f);
    }
}

// ============================================================
// 2b) Wh transpose: g_whT[l][c][k] = Wh[l][k][c]
// ============================================================
__global__ void k_whT(const float* __restrict__ Wh)
{
    __shared__ float tile[32][33];
    int l = blockIdx.z;
    const float* src = Wh + (size_t)l*D_*GD_;
    float* dst = g_whT + (size_t)l*GD_*D_;
    int c0 = blockIdx.x*32, k0 = blockIdx.y*32;
    int tx = threadIdx.x, ty = threadIdx.y;
    #pragma unroll
    for(int r=0;r<32;r+=8) tile[ty+r][tx] = src[(size_t)(k0+ty+r)*GD_ + c0+tx];
    __syncthreads();
    #pragma unroll
    for(int r=0;r<32;r+=8) dst[(size_t)(c0+ty+r)*D_ + k0+tx] = tile[tx][ty+r];
}

// ============================================================
// 3) gx = (LN(h)*g+b) @ Wx + bg   (128x128 tile, f32x2 accs)
// ============================================================
__global__ __launch_bounds__(256)
void k_gemm(const float* __restrict__ Wx, const float* __restrict__ bg,
            const float* __restrict__ lng, const float* __restrict__ lnb)
{
    __shared__ __align__(16) float As[8*128];
    __shared__ __align__(16) float Bs[8*128];

    int tid = threadIdx.x;
    int m0 = blockIdx.y*128, n0 = blockIdx.x*128;
    int tx = tid & 15, ty = tid >> 4;

    ull acc[8][4];
    #pragma unroll
    for(int i=0;i<8;i++)
        #pragma unroll
        for(int j=0;j<4;j++) acc[i][j]=0ULL;

    int arow = tid>>1, akp = (tid&1)*4;
    float amu = g_mu[m0+arow], ars = g_rs[m0+arow];
    int bkk = tid>>5, bn = (tid&31)*4;

    for(int kb=0; kb<D_; kb+=8){
        float4 av = *(const float4*)(g_h + (size_t)(m0+arow)*D_ + kb + akp);
        float4 lg = *(const float4*)(lng + kb + akp);
        float4 lb = *(const float4*)(lnb + kb + akp);
        As[(akp+0)*128+arow] = (av.x-amu)*ars*lg.x + lb.x;
        As[(akp+1)*128+arow] = (av.y-amu)*ars*lg.y + lb.y;
        As[(akp+2)*128+arow] = (av.z-amu)*ars*lg.z + lb.z;
        As[(akp+3)*128+arow] = (av.w-amu)*ars*lg.w + lb.w;
        *(float4*)(Bs + bkk*128 + bn) =
            *(const float4*)(Wx + (size_t)(kb+bkk)*GD_ + n0 + bn);
        __syncthreads();
        #pragma unroll
        for(int kk=0; kk<8; kk++){
            float4 a0 = *(const float4*)(As + kk*128 + ty*8);
            float4 a1 = *(const float4*)(As + kk*128 + ty*8 + 4);
            const ull* b2 = (const ull*)(Bs + kk*128 + tx*8);
            ull bb0=b2[0], bb1=b2[1], bb2=b2[2], bb3=b2[3];
            float a[8] = {a0.x,a0.y,a0.z,a0.w,a1.x,a1.y,a1.z,a1.w};
            #pragma unroll
            for(int i=0;i<8;i++){
                ull a2 = pack2(a[i], a[i]);
                fma2(acc[i][0], a2, bb0);
                fma2(acc[i][1], a2, bb1);
                fma2(acc[i][2], a2, bb2);
                fma2(acc[i][3], a2, bb3);
            }
        }
        __syncthreads();
    }
    float4 bg0 = *(const float4*)(bg + n0 + tx*8);
    float4 bg1 = *(const float4*)(bg + n0 + tx*8 + 4);
    #pragma unroll
    for(int i=0;i<8;i++){
        float* C = g_gx + (size_t)(m0+ty*8+i)*GD_ + n0 + tx*8;
        float2 c0=unpack2(acc[i][0]), c1=unpack2(acc[i][1]);
        float2 c2=unpack2(acc[i][2]), c3=unpack2(acc[i][3]);
        *(float4*)C       = make_float4(c0.x+bg0.x, c0.y+bg0.y, c1.x+bg0.z, c1.y+bg0.w);
        *(float4*)(C + 4) = make_float4(c2.x+bg1.x, c2.y+bg1.y, c3.x+bg1.z, c3.y+bg1.w);
    }
}

// ============================================================
// 4) sLSTM recurrence — warp-autonomous pipeline, mbarrier sync.
//    Cluster 8, 256 thr/CTA. Warp w owns dims rank*32+4w..+4,
//    all 4 gates (16 cols, 2 threads/col over k). Gating warp-local.
//    Publication: lane0 st.shared::cluster.v4 to 8 peers, syncwarp,
//    lanes0-7 remote mbarrier.arrive.release.cluster (count 64).
//    Consumers: LOCAL mbarrier.try_wait.parity (HW sleep).
//    NO __syncthreads / cluster barrier in the 2048-step loop.
// ============================================================

#define SSTEP(T, CUR, MBL, PH, RH, RMB)                                        \
{                                                                              \
    /* ---- wait: all 64 producer warps arrived for this buffer/phase */       \
    asm volatile(                                                              \
        "{\n\t.reg .pred P;\n\t"                                               \
        "WL_%=:\n\t"                                                           \
        "mbarrier.try_wait.parity.acquire.cta.shared::cta.b64 P, [%0], %1, 0x989680;\n\t" \
        "@P bra.uni WD_%=;\n\t"                                                \
        "bra.uni WL_%=;\n\t"                                                   \
        "WD_%=:\n\t}"                                                          \
        :: "r"(MBL), "r"(PH) : "memory");                                      \
    PH ^= 1;                                                                   \
    asm volatile("cp.async.wait_group 3;" ::: "memory");                       \
    __syncwarp();                                                              \
    /* ---- consume prefetched gx / residual for this step */                  \
    int slot = (T) & 3;                                                        \
    float gxi=0.f,gxf=0.f,gxz=0.f,gxo=0.f,hres=0.f;                            \
    if(lane < 4){                                                              \
        const float* gb = &gxbuf[slot][warp*16 + lane];                        \
        gxi = gb[0]; gxf = gb[4]; gxz = gb[8]; gxo = gb[12];                   \
        hres = hrbuf[slot][warp*4 + lane];                                     \
    }                                                                          \
    __syncwarp();                                                              \
    /* ---- refill slot with step T+4 */                                       \
    if((T)+4 < S_){                                                            \
        if(lane < 4){                                                          \
            uint32_t dgx = gxsa + (uint32_t)slot*512u;                         \
            const float* sg = gx_b + (size_t)((T)+4)*GD_ + gx_off;             \
            asm volatile("cp.async.cg.shared.global [%0], [%1], 16;"           \
                         :: "r"(dgx), "l"(sg));                                \
        } else if(lane == 4){                                                  \
            uint32_t dhr = hrsa + (uint32_t)slot*128u;                         \
            const float* sh = h_bp + (size_t)((T)+4)*D_ + hr_off;              \
            asm volatile("cp.async.cg.shared.global [%0], [%1], 16;"           \
                         :: "r"(dhr), "l"(sh));                                \
        }                                                                      \
    }                                                                          \
    asm volatile("cp.async.commit_group;" ::: "memory");                       \
    /* ---- matvec over my k-half for my 16 columns' share */                  \
    const ull* hu = (const ull*)h_buf[CUR];                                    \
    ull a0=0ULL, a1=0ULL, a2v=0ULL, a3=0ULL;                                   \
    _Pragma("unroll")                                                          \
    for(int q=0; q<16; q++){                                                   \
        ulonglong2 U = *(const ulonglong2*)(hu + 8*q + 4*s);                   \
        ulonglong2 V = *(const ulonglong2*)(hu + 8*q + 4*s + 2);               \
        fma2(a0,  U.x, w[4*q+0]);                                              \
        fma2(a1,  U.y, w[4*q+1]);                                              \
        fma2(a2v, V.x, w[4*q+2]);                                              \
        fma2(a3,  V.y, w[4*q+3]);                                              \
    }                                                                          \
    add2(a0, a1); add2(a2v, a3); add2(a0, a2v);                                \
    float2 pp = unpack2(a0);                                                   \
    float v = pp.x + pp.y;                                                     \
    v += __shfl_xor_sync(FULLM, v, 16);                                        \
    /* ---- gather gates to lanes 0..3 (dim j) */                              \
    int src4 = 4*lane;                                                         \
    float vi = __shfl_sync(FULLM, v, src4    );                                \
    float vf = __shfl_sync(FULLM, v, src4 + 1);                                \
    float vz = __shfl_sync(FULLM, v, src4 + 2);                                \
    float vo = __shfl_sync(FULLM, v, src4 + 3);                                \
    float hval = 0.f;                                                          \
    if(lane < 4){                                                              \
        float i_t = vi + gxi, f_t = vf + gxf;                                  \
        float z_t = vz + gxz, o_t = vo + gxo;                                  \
        float m_new = fmaxf(f_t + m_st, i_t);                                  \
        float ip = __expf(i_t - m_new);                                        \
        float fp = __expf(f_t + m_st - m_new);                                 \
        m_st = m_new;                                                          \
        c_st = fp*c_st + ip*ftanh(z_t);                                        \
        n_st = fp*n_st + ip;                                                   \
        float sig  = frcp(1.f + __expf(-o_t));                                 \
        hval = sig * c_st * frcp(fmaxf(fabsf(n_st), 1.f));                     \
        h_bp[(size_t)(T)*D_ + hr_off + lane] = hres + hval;                    \
    }                                                                          \
    /* ---- publish: v4 push to 8 peers, then release-arrive their mbar */     \
    if((T)+1 < S_){                                                            \
        float h4x = __shfl_sync(FULLM, hval, 0);                               \
        float h4y = __shfl_sync(FULLM, hval, 1);                               \
        float h4z = __shfl_sync(FULLM, hval, 2);                               \
        float h4w = __shfl_sync(FULLM, hval, 3);                               \
        if(lane == 0){                                                         \
            _Pragma("unroll")                                                  \
            for(int r=0; r<CL; r++)                                            \
                asm volatile("st.shared::cluster.v4.f32 [%0], {%1,%2,%3,%4};"  \
                             :: "r"(RH[r]), "f"(h4x), "f"(h4y),                \
                                "f"(h4z), "f"(h4w) : "memory");                \
        }                                                                      \
        __syncwarp();                                                          \
        if(lane < 8)                                                           \
            asm volatile("mbarrier.arrive.release.cluster.shared::cluster.b64 _, [%0];" \
                         :: "r"(RMB) : "memory");                              \
    }                                                                          \
}

__global__ void __launch_bounds__(256,1) __cluster_dims__(CL,1,1)
k_slstm(int layer)
{
    __shared__ __align__(16) float h_buf[2][256];   // [buf][dim]
    __shared__ __align__(8)  ull   mbar[2];         // [buf] arrival barrier (count 64)
    __shared__ __align__(16) float gxbuf[4][128];   // [slot][warp*16 + gate*4 + j]
    __shared__ __align__(16) float hrbuf[4][32];    // [slot][warp*4 + j]

    int tid  = threadIdx.x;
    int lane = tid & 31, warp = tid >> 5;
    uint32_t rank;
    asm("mov.u32 %0, %%cluster_ctarank;" : "=r"(rank));
    int batch = blockIdx.x >> 3;

    // column assignment: warp owns dims rank*32+4w..+4, all 4 gates.
    int cw = lane & 15;                 // col within warp
    int s  = lane >> 4;                 // k-half (16-float interleave)
    int dim_l = cw >> 2, gate = cw & 3;
    int gcol = gate*256 + (int)rank*32 + warp*4 + dim_l;

    // register-resident Wh^T: my column's k-half (128 values, 64 f32x2)
    const float* wr = g_whT + (size_t)layer*GD_*D_ + (size_t)gcol*D_;
    ull w[64];
    #pragma unroll
    for(int q=0; q<16; q++){
        float4 A  = *(const float4*)(wr + 16*q + 8*s);
        float4 Bv = *(const float4*)(wr + 16*q + 8*s + 4);
        w[4*q+0] = pack2(A.x,  A.y);
        w[4*q+1] = pack2(A.z,  A.w);
        w[4*q+2] = pack2(Bv.x, Bv.y);
        w[4*q+3] = pack2(Bv.z, Bv.w);
    }

    const float* gx_b = g_gx + (size_t)batch*S_*GD_;
    float*       h_bp = g_h  + (size_t)batch*S_*D_;
    int gx_off = lane*256 + (int)rank*32 + warp*4;   // valid for lane<4
    int hr_off = (int)rank*32 + warp*4;

    // hoisted remote addresses
    uint32_t rh0[CL], rh1[CL], rmb0, rmb1;
    {
        uint32_t l0 = (uint32_t)__cvta_generic_to_shared(&h_buf[0][(int)rank*32 + warp*4]);
        uint32_t l1 = l0 + 1024u;   // h_buf[1]
        #pragma unroll
        for(int r=0; r<CL; r++){
            asm volatile("mapa.shared::cluster.u32 %0, %1, %2;" : "=r"(rh0[r]) : "r"(l0), "r"(r));
            asm volatile("mapa.shared::cluster.u32 %0, %1, %2;" : "=r"(rh1[r]) : "r"(l1), "r"(r));
        }
        uint32_t lm0 = (uint32_t)__cvta_generic_to_shared(&mbar[0]);
        int peer = lane & 7;
        asm volatile("mapa.shared::cluster.u32 %0, %1, %2;" : "=r"(rmb0) : "r"(lm0),      "r"(peer));
        asm volatile("mapa.shared::cluster.u32 %0, %1, %2;" : "=r"(rmb1) : "r"(lm0 + 8u), "r"(peer));
    }
    uint32_t mbl0 = (uint32_t)__cvta_generic_to_shared(&mbar[0]);
    uint32_t mbl1 = mbl0 + 8u;
    // cp.async destinations
    uint32_t gxsa = (uint32_t)__cvta_generic_to_shared(&gxbuf[0][warp*16 + lane*4]); // lane<4
    uint32_t hrsa = (uint32_t)__cvta_generic_to_shared(&hrbuf[0][warp*4]);           // lane==4

    // init: zero h_buf[0], init both mbarriers (count 64 = 8 warps x 8 CTAs)
    h_buf[0][tid] = 0.f;
    if(tid == 0){
        asm volatile("mbarrier.init.shared.b64 [%0], %1;" :: "r"(mbl0), "r"(64) : "memory");
        asm volatile("mbarrier.init.shared.b64 [%0], %1;" :: "r"(mbl1), "r"(64) : "memory");
    }
    __syncthreads();
    asm volatile("barrier.cluster.arrive.aligned;" ::: "memory");
    asm volatile("barrier.cluster.wait.aligned;"   ::: "memory");

    // prime buffer 0: every producer warp arrives at all peers' mbar[0]
    if(lane < 8)
        asm volatile("mbarrier.arrive.release.cluster.shared::cluster.b64 _, [%0];"
                     :: "r"(rmb0) : "memory");

    // prefill cp.async ring: steps 0..3
    #pragma unroll
    for(int pt=0; pt<4; pt++){
        if(lane < 4){
            uint32_t dgx = gxsa + (uint32_t)pt*512u;
            const float* sg = gx_b + (size_t)pt*GD_ + gx_off;
            asm volatile("cp.async.cg.shared.global [%0], [%1], 16;" :: "r"(dgx), "l"(sg));
        } else if(lane == 4){
            uint32_t dhr = hrsa + (uint32_t)pt*128u;
            const float* sh = h_bp + (size_t)pt*D_ + hr_off;
            asm volatile("cp.async.cg.shared.global [%0], [%1], 16;" :: "r"(dhr), "l"(sh));
        }
        asm volatile("cp.async.commit_group;" ::: "memory");
    }

    float c_st=0.f, n_st=0.f, m_st=0.f;
    int ph0 = 0, ph1 = 0;

    for(int t=0; t<S_; t+=2){
        SSTEP(t,   0, mbl0, ph0, rh1, rmb1)
        SSTEP(t+1, 1, mbl1, ph1, rh0, rmb0)
    }

    // keep cluster SMEM alive until all CTAs' in-flight pushes have landed
    asm volatile("barrier.cluster.arrive.aligned;" ::: "memory");
    asm volatile("barrier.cluster.wait.aligned;"   ::: "memory");
}

// ============================================================
// 5) head: out[b] = h[b, S-1, :] @ fc_W + fc_b
// ============================================================
__global__ void k_head(const float* __restrict__ fcW, const float* __restrict__ fcb,
                       float* __restrict__ out)
{
    __shared__ float red[8];
    int b = blockIdx.x, tid = threadIdx.x;
    int lane = tid & 31, warp = tid >> 5;
    float v = g_h[((size_t)b*S_ + (S_-1))*D_ + tid] * fcW[tid];
    #pragma unroll
    for(int o=16;o;o>>=1) v += __shfl_xor_sync(~0u, v, o);
    if(lane==0) red[warp] = v;
    __syncthreads();
    if(tid==0){
        float s = 0.f;
        #pragma unroll
        for(int w=0;w<8;w++) s += red[w];
        out[b] = s + fcb[0];
    }
}

// ============================================================
extern "C" void kernel_launch(void* const* d_in, const int* in_sizes, int n_in,
                              void* d_out, int out_size)
{
    (void)in_sizes; (void)n_in; (void)out_size;
    const float* x    = (const float*)d_in[0];
    const float* tf   = (const float*)d_in[1];
    const float* in_W = (const float*)d_in[2];
    const float* in_b = (const float*)d_in[3];
    const float* ln_g = (const float*)d_in[4];
    const float* ln_b = (const float*)d_in[5];
    const float* Wx   = (const float*)d_in[6];
    const float* Wh   = (const float*)d_in[7];
    const float* bg   = (const float*)d_in[8];
    const float* fc_W = (const float*)d_in[9];
    const float* fc_b = (const float*)d_in[10];
    float* out = (float*)d_out;

    k_inproj<<<NTOK, 256>>>(x, tf, in_W, in_b);
    k_whT<<<dim3(GD_/32, D_/32, L_), dim3(32,8)>>>(Wh);
    for(int l=0; l<L_; l++){
        k_lnstats<<<NTOK/8, 256>>>();
        k_gemm<<<dim3(8,256), 256>>>(Wx + (size_t)l*D_*GD_, bg + (size_t)l*GD_,
                                     ln_g + (size_t)l*D_, ln_b + (size_t)l*D_);
        k_slstm<<<B_*CL, 256>>>(l);
    }
    k_head<<<B_, 256>>>(fc_W, fc_b, out);
}

// round 15
// speedup vs baseline: 1.9311x; 1.2926x over previous
#include <cuda_runtime.h>
#include <cuda_bf16.h>
#include <cstdint>
#include <cstddef>

#define B_   16
#define S_   2048
#define D_   256
#define GD_  1024
#define L_   4
#define NTOK (B_*S_)
#define CL   8
#define FULLM 0xffffffffu

// ---- scratch (device globals: no allocations allowed) ----
__device__ float g_h  [(size_t)NTOK*D_];      // residual stream [B,S,D]
__device__ float g_gx [(size_t)NTOK*GD_];     // gate preacts    [B,S,4D]
__device__ float g_mu [NTOK];
__device__ float g_rs [NTOK];
__device__ float g_whT[(size_t)L_*GD_*D_];    // Wh transposed: [l][col][k]

typedef unsigned long long ull;

__device__ __forceinline__ ull pack2(float x, float y){
    ull r; asm("mov.b64 %0,{%1,%2};" : "=l"(r) : "f"(x), "f"(y)); return r;
}
__device__ __forceinline__ float2 unpack2(ull v){
    float2 f; asm("mov.b64 {%0,%1},%2;" : "=f"(f.x), "=f"(f.y) : "l"(v)); return f;
}
__device__ __forceinline__ void fma2(ull& d, ull a, ull b){
    asm("fma.rn.f32x2 %0,%1,%2,%0;" : "+l"(d) : "l"(a), "l"(b));
}
__device__ __forceinline__ void add2(ull& d, ull a){
    asm("add.rn.f32x2 %0,%0,%1;" : "+l"(d) : "l"(a));
}
__device__ __forceinline__ float frcp(float x){
    float r; asm("rcp.approx.f32 %0,%1;" : "=f"(r) : "f"(x)); return r;
}
__device__ __forceinline__ float ftanh(float x){
    float r; asm("tanh.approx.f32 %0,%1;" : "=f"(r) : "f"(x)); return r;
}

// ============================================================
// 1) input projection
// ============================================================
__global__ void k_inproj(const float* __restrict__ x, const float* __restrict__ tf,
                         const float* __restrict__ W, const float* __restrict__ b)
{
    int t = blockIdx.x, d = threadIdx.x;
    float acc = b[d] + x[t]*W[d];
    const float* tft = tf + (size_t)t*6;
    #pragma unroll
    for(int f=0; f<6; f++) acc = fmaf(tft[f], W[(f+1)*D_ + d], acc);
    g_h[(size_t)t*D_ + d] = acc;
}

// ============================================================
// 2) per-token layernorm stats
// ============================================================
__global__ void k_lnstats()
{
    int warp = threadIdx.x >> 5, lane = threadIdx.x & 31;
    int t = blockIdx.x*8 + warp;
    const float4* p = (const float4*)(g_h + (size_t)t*D_) + lane*2;
    float4 v0 = p[0], v1 = p[1];
    float s = v0.x+v0.y+v0.z+v0.w + v1.x+v1.y+v1.z+v1.w;
    float q = v0.x*v0.x+v0.y*v0.y+v0.z*v0.z+v0.w*v0.w
            + v1.x*v1.x+v1.y*v1.y+v1.z*v1.z+v1.w*v1.w;
    #pragma unroll
    for(int o=16;o;o>>=1){ s += __shfl_xor_sync(~0u,s,o); q += __shfl_xor_sync(~0u,q,o); }
    if(lane==0){
        float mu  = s * (1.f/256.f);
        float var = q * (1.f/256.f) - mu*mu;
        g_mu[t] = mu;
        g_rs[t] = rsqrtf(var + 1e-5f);
    }
}

// ============================================================
// 2b) Wh transpose: g_whT[l][c][k] = Wh[l][k][c]
// ============================================================
__global__ void k_whT(const float* __restrict__ Wh)
{
    __shared__ float tile[32][33];
    int l = blockIdx.z;
    const float* src = Wh + (size_t)l*D_*GD_;
    float* dst = g_whT + (size_t)l*GD_*D_;
    int c0 = blockIdx.x*32, k0 = blockIdx.y*32;
    int tx = threadIdx.x, ty = threadIdx.y;
    #pragma unroll
    for(int r=0;r<32;r+=8) tile[ty+r][tx] = src[(size_t)(k0+ty+r)*GD_ + c0+tx];
    __syncthreads();
    #pragma unroll
    for(int r=0;r<32;r+=8) dst[(size_t)(c0+ty+r)*D_ + k0+tx] = tile[tx][ty+r];
}

// ============================================================
// 3) gx = (LN(h)*g+b) @ Wx + bg   (128x128 tile, f32x2 accs)
// ============================================================
__global__ __launch_bounds__(256)
void k_gemm(const float* __restrict__ Wx, const float* __restrict__ bg,
            const float* __restrict__ lng, const float* __restrict__ lnb)
{
    __shared__ __align__(16) float As[8*128];
    __shared__ __align__(16) float Bs[8*128];

    int tid = threadIdx.x;
    int m0 = blockIdx.y*128, n0 = blockIdx.x*128;
    int tx = tid & 15, ty = tid >> 4;

    ull acc[8][4];
    #pragma unroll
    for(int i=0;i<8;i++)
        #pragma unroll
        for(int j=0;j<4;j++) acc[i][j]=0ULL;

    int arow = tid>>1, akp = (tid&1)*4;
    float amu = g_mu[m0+arow], ars = g_rs[m0+arow];
    int bkk = tid>>5, bn = (tid&31)*4;

    for(int kb=0; kb<D_; kb+=8){
        float4 av = *(const float4*)(g_h + (size_t)(m0+arow)*D_ + kb + akp);
        float4 lg = *(const float4*)(lng + kb + akp);
        float4 lb = *(const float4*)(lnb + kb + akp);
        As[(akp+0)*128+arow] = (av.x-amu)*ars*lg.x + lb.x;
        As[(akp+1)*128+arow] = (av.y-amu)*ars*lg.y + lb.y;
        As[(akp+2)*128+arow] = (av.z-amu)*ars*lg.z + lb.z;
        As[(akp+3)*128+arow] = (av.w-amu)*ars*lg.w + lb.w;
        *(float4*)(Bs + bkk*128 + bn) =
            *(const float4*)(Wx + (size_t)(kb+bkk)*GD_ + n0 + bn);
        __syncthreads();
        #pragma unroll
        for(int kk=0; kk<8; kk++){
            float4 a0 = *(const float4*)(As + kk*128 + ty*8);
            float4 a1 = *(const float4*)(As + kk*128 + ty*8 + 4);
            const ull* b2 = (const ull*)(Bs + kk*128 + tx*8);
            ull bb0=b2[0], bb1=b2[1], bb2=b2[2], bb3=b2[3];
            float a[8] = {a0.x,a0.y,a0.z,a0.w,a1.x,a1.y,a1.z,a1.w};
            #pragma unroll
            for(int i=0;i<8;i++){
                ull a2 = pack2(a[i], a[i]);
                fma2(acc[i][0], a2, bb0);
                fma2(acc[i][1], a2, bb1);
                fma2(acc[i][2], a2, bb2);
                fma2(acc[i][3], a2, bb3);
            }
        }
        __syncthreads();
    }
    float4 bg0 = *(const float4*)(bg + n0 + tx*8);
    float4 bg1 = *(const float4*)(bg + n0 + tx*8 + 4);
    #pragma unroll
    for(int i=0;i<8;i++){
        float* C = g_gx + (size_t)(m0+ty*8+i)*GD_ + n0 + tx*8;
        float2 c0=unpack2(acc[i][0]), c1=unpack2(acc[i][1]);
        float2 c2=unpack2(acc[i][2]), c3=unpack2(acc[i][3]);
        *(float4*)C       = make_float4(c0.x+bg0.x, c0.y+bg0.y, c1.x+bg0.z, c1.y+bg0.w);
        *(float4*)(C + 4) = make_float4(c2.x+bg1.x, c2.y+bg1.y, c3.x+bg1.z, c3.y+bg1.w);
    }
}

// ============================================================
// 4) sLSTM recurrence — warp-autonomous compute + split
//    barrier.cluster per step (arrive -> shadow work -> wait).
//    Cluster 8, 256 thr/CTA. Warp w owns dims rank*32+4w..+3,
//    all 4 gates (16 cols, 2 thr/col over k). Gating warp-local
//    on lanes 0-3. NO __syncthreads / mbarrier in the loop.
// ============================================================

#define SSTEP(T, CUR, RH)                                                      \
{                                                                              \
    /* ---- matvec: my 16 cols' k-half over h_buf[CUR] */                      \
    const ull* hu = (const ull*)h_buf[CUR];                                    \
    ull a0=0ULL, a1=0ULL, a2v=0ULL, a3=0ULL;                                   \
    _Pragma("unroll")                                                          \
    for(int q=0; q<16; q++){                                                   \
        ulonglong2 U = *(const ulonglong2*)(hu + 8*q + 4*s);                   \
        ulonglong2 V = *(const ulonglong2*)(hu + 8*q + 4*s + 2);               \
        fma2(a0,  U.x, w[4*q+0]);                                              \
        fma2(a1,  U.y, w[4*q+1]);                                              \
        fma2(a2v, V.x, w[4*q+2]);                                              \
        fma2(a3,  V.y, w[4*q+3]);                                              \
    }                                                                          \
    add2(a0, a1); add2(a2v, a3); add2(a0, a2v);                                \
    float2 pp = unpack2(a0);                                                   \
    float v = pp.x + pp.y;                                                     \
    v += __shfl_xor_sync(FULLM, v, 16);                                        \
    /* ---- gather gates to lanes 0..3 (dim j) */                              \
    int src4 = 4*lane;                                                         \
    float vi = __shfl_sync(FULLM, v, src4    );                                \
    float vf = __shfl_sync(FULLM, v, src4 + 1);                                \
    float vz = __shfl_sync(FULLM, v, src4 + 2);                                \
    float vo = __shfl_sync(FULLM, v, src4 + 3);                                \
    float hval = 0.f;                                                          \
    if(lane < 4){                                                              \
        float i_t = vi + gxi, f_t = vf + gxf;                                  \
        float z_t = vz + gxz, o_t = vo + gxo;                                  \
        float m_new = fmaxf(f_t + m_st, i_t);                                  \
        float ip = __expf(i_t - m_new);                                        \
        float fp = __expf(f_t + m_st - m_new);                                 \
        m_st = m_new;                                                          \
        c_st = fp*c_st + ip*ftanh(z_t);                                        \
        n_st = fp*n_st + ip;                                                   \
        float sig  = frcp(1.f + __expf(-o_t));                                 \
        hval = sig * c_st * frcp(fmaxf(fabsf(n_st), 1.f));                     \
    }                                                                          \
    /* ---- pack 4 dims, push to all 8 CTAs' buffer[nxt] */                    \
    float h4x = __shfl_sync(FULLM, hval, 0);                                   \
    float h4y = __shfl_sync(FULLM, hval, 1);                                   \
    float h4z = __shfl_sync(FULLM, hval, 2);                                   \
    float h4w = __shfl_sync(FULLM, hval, 3);                                   \
    if(lane == 0){                                                             \
        _Pragma("unroll")                                                      \
        for(int r=0; r<CL; r++)                                                \
            asm volatile("st.shared::cluster.v4.f32 [%0], {%1,%2,%3,%4};"      \
                         :: "r"(RH[r]), "f"(h4x), "f"(h4y),                    \
                            "f"(h4z), "f"(h4w) : "memory");                    \
    }                                                                          \
    asm volatile("barrier.cluster.arrive.aligned;" ::: "memory");              \
    /* ---- shadow work (hidden under barrier latency) ---- */                 \
    if(lane < 4) h_bp[(size_t)(T)*D_ + hr_off + lane] = hres + hval;           \
    asm volatile("cp.async.wait_group 3;" ::: "memory");                       \
    __syncwarp();                                                              \
    int slot = ((T)+1) & 3;                                                    \
    if((T)+1 < S_ && lane < 4){                                                \
        const float* gb = &gxbuf[slot][warp][0];                               \
        gxi = gb[lane]; gxf = gb[4+lane]; gxz = gb[8+lane]; gxo = gb[12+lane]; \
        hres = hrbuf[slot][warp][lane];                                        \
    }                                                                          \
    if((T)+5 < S_){                                                            \
        if(lane < 4){                                                          \
            uint32_t dgx = gxsa + (uint32_t)slot*512u;                         \
            const float* sg = gx_b + (size_t)((T)+5)*GD_ + gx_off;             \
            asm volatile("cp.async.cg.shared.global [%0], [%1], 16;"           \
                         :: "r"(dgx), "l"(sg));                                \
        } else if(lane == 4){                                                  \
            uint32_t dhr = hrsa + (uint32_t)slot*128u;                         \
            const float* sh = h_bp + (size_t)((T)+5)*D_ + hr_off;              \
            asm volatile("cp.async.cg.shared.global [%0], [%1], 16;"           \
                         :: "r"(dhr), "l"(sh));                                \
        }                                                                      \
    }                                                                          \
    asm volatile("cp.async.commit_group;" ::: "memory");                       \
    asm volatile("barrier.cluster.wait.aligned;" ::: "memory");                \
}

__global__ void __launch_bounds__(256,1) __cluster_dims__(CL,1,1)
k_slstm(int layer)
{
    __shared__ __align__(16) float h_buf[2][256];   // [buf][dim]
    __shared__ __align__(16) float gxbuf[4][8][16]; // [slot][warp][gate*4+j]
    __shared__ __align__(16) float hrbuf[4][8][4];  // [slot][warp][j]

    int tid  = threadIdx.x;
    int lane = tid & 31, warp = tid >> 5;
    uint32_t rank;
    asm("mov.u32 %0, %%cluster_ctarank;" : "=r"(rank));
    int batch = blockIdx.x >> 3;

    // column assignment: warp owns dims rank*32+4w..+3, all 4 gates.
    int cw = lane & 15;                 // col within warp (= dim_l*4 + gate)
    int s  = lane >> 4;                 // k-half (16-float interleave)
    int dim_l = cw >> 2, gate = cw & 3;
    int gcol = gate*256 + (int)rank*32 + warp*4 + dim_l;

    // register-resident Wh^T: my column's k-half (128 values, 64 f32x2)
    const float* wr = g_whT + (size_t)layer*GD_*D_ + (size_t)gcol*D_;
    ull w[64];
    #pragma unroll
    for(int q=0; q<16; q++){
        float4 A  = *(const float4*)(wr + 16*q + 8*s);
        float4 Bv = *(const float4*)(wr + 16*q + 8*s + 4);
        w[4*q+0] = pack2(A.x,  A.y);
        w[4*q+1] = pack2(A.z,  A.w);
        w[4*q+2] = pack2(Bv.x, Bv.y);
        w[4*q+3] = pack2(Bv.z, Bv.w);
    }

    const float* gx_b = g_gx + (size_t)batch*S_*GD_;
    float*       h_bp = g_h  + (size_t)batch*S_*D_;
    int gx_off = lane*256 + (int)rank*32 + warp*4;   // valid for lane<4 (lane = gate)
    int hr_off = (int)rank*32 + warp*4;

    // hoisted remote push addresses (lane 0 of each warp pushes 16B)
    uint32_t rh0[CL], rh1[CL];
    {
        uint32_t l0 = (uint32_t)__cvta_generic_to_shared(&h_buf[0][(int)rank*32 + warp*4]);
        uint32_t l1 = l0 + 1024u;   // h_buf[1]
        #pragma unroll
        for(int r=0; r<CL; r++){
            asm volatile("mapa.shared::cluster.u32 %0, %1, %2;" : "=r"(rh0[r]) : "r"(l0), "r"(r));
            asm volatile("mapa.shared::cluster.u32 %0, %1, %2;" : "=r"(rh1[r]) : "r"(l1), "r"(r));
        }
    }
    // cp.async destinations
    uint32_t gxsa = (uint32_t)__cvta_generic_to_shared(&gxbuf[0][warp][lane*4]); // lane<4
    uint32_t hrsa = (uint32_t)__cvta_generic_to_shared(&hrbuf[0][warp][0]);      // lane==4

    // init local h_buf[0]
    h_buf[0][tid] = 0.f;

    // prefill cp.async ring: slots 0..3 <- steps 0..3
    #pragma unroll
    for(int pt=0; pt<4; pt++){
        if(lane < 4){
            uint32_t dgx = gxsa + (uint32_t)pt*512u;
            const float* sg = gx_b + (size_t)pt*GD_ + gx_off;
            asm volatile("cp.async.cg.shared.global [%0], [%1], 16;" :: "r"(dgx), "l"(sg));
        } else if(lane == 4){
            uint32_t dhr = hrsa + (uint32_t)pt*128u;
            const float* sh = h_bp + (size_t)pt*D_ + hr_off;
            asm volatile("cp.async.cg.shared.global [%0], [%1], 16;" :: "r"(dhr), "l"(sh));
        }
        asm volatile("cp.async.commit_group;" ::: "memory");
    }
    __syncthreads();   // h_buf[0] + ring init visible CTA-wide

    // prologue: consume slot 0 (t=0), refill slot 0 <- t=4
    float gxi=0.f, gxf=0.f, gxz=0.f, gxo=0.f, hres=0.f;
    asm volatile("cp.async.wait_group 3;" ::: "memory");
    __syncwarp();
    if(lane < 4){
        const float* gb = &gxbuf[0][warp][0];
        gxi = gb[lane]; gxf = gb[4+lane]; gxz = gb[8+lane]; gxo = gb[12+lane];
        hres = hrbuf[0][warp][lane];
    }
    if(lane < 4){
        const float* sg = gx_b + (size_t)4*GD_ + gx_off;
        asm volatile("cp.async.cg.shared.global [%0], [%1], 16;" :: "r"(gxsa), "l"(sg));
    } else if(lane == 4){
        const float* sh = h_bp + (size_t)4*D_ + hr_off;
        asm volatile("cp.async.cg.shared.global [%0], [%1], 16;" :: "r"(hrsa), "l"(sh));
    }
    asm volatile("cp.async.commit_group;" ::: "memory");

    float c_st=0.f, n_st=0.f, m_st=0.f;

    for(int t=0; t<S_; t+=2){
        SSTEP(t,   0, rh1)
        SSTEP(t+1, 1, rh0)
    }
}

// ============================================================
// 5) head: out[b] = h[b, S-1, :] @ fc_W + fc_b
// ============================================================
__global__ void k_head(const float* __restrict__ fcW, const float* __restrict__ fcb,
                       float* __restrict__ out)
{
    __shared__ float red[8];
    int b = blockIdx.x, tid = threadIdx.x;
    int lane = tid & 31, warp = tid >> 5;
    float v = g_h[((size_t)b*S_ + (S_-1))*D_ + tid] * fcW[tid];
    #pragma unroll
    for(int o=16;o;o>>=1) v += __shfl_xor_sync(~0u, v, o);
    if(lane==0) red[warp] = v;
    __syncthreads();
    if(tid==0){
        float s = 0.f;
        #pragma unroll
        for(int w=0;w<8;w++) s += red[w];
        out[b] = s + fcb[0];
    }
}

// ============================================================
extern "C" void kernel_launch(void* const* d_in, const int* in_sizes, int n_in,
                              void* d_out, int out_size)
{
    (void)in_sizes; (void)n_in; (void)out_size;
    const float* x    = (const float*)d_in[0];
    const float* tf   = (const float*)d_in[1];
    const float* in_W = (const float*)d_in[2];
    const float* in_b = (const float*)d_in[3];
    const float* ln_g = (const float*)d_in[4];
    const float* ln_b = (const float*)d_in[5];
    const float* Wx   = (const float*)d_in[6];
    const float* Wh   = (const float*)d_in[7];
    const float* bg   = (const float*)d_in[8];
    const float* fc_W = (const float*)d_in[9];
    const float* fc_b = (const float*)d_in[10];
    float* out = (float*)d_out;

    k_inproj<<<NTOK, 256>>>(x, tf, in_W, in_b);
    k_whT<<<dim3(GD_/32, D_/32, L_), dim3(32,8)>>>(Wh);
    for(int l=0; l<L_; l++){
        k_lnstats<<<NTOK/8, 256>>>();
        k_gemm<<<dim3(8,256), 256>>>(Wx + (size_t)l*D_*GD_, bg + (size_t)l*GD_,
                                     ln_g + (size_t)l*D_, ln_b + (size_t)l*D_);
        k_slstm<<<B_*CL, 256>>>(l);
    }
    k_head<<<B_, 256>>>(fc_W, fc_b, out);
}